// round 2
// baseline (speedup 1.0000x reference)
#include <cuda_runtime.h>
#include <math.h>

#define SEQN 512
#define BATN 64
#define KIN  1024
#define HN   1024
#define STEP_ELEMS (BATN * HN)          // 65536 floats per timestep

// Persistent recurrence decomposition
#define NBLK 128                        // total blocks (co-resident on 148/152 SMs)
#define KSPL 8                          // K splits
#define NSPL 16                         // N splits
#define NS   64                         // columns per block
#define KSL  128                        // k-range per block

// Split-K partial buffer: [KSPL][BATN][HN] = 2 MB
__device__ float g_part[KSPL * BATN * HN];

// Grid barrier state (zero-initialized; returns to zero after each call)
__device__ volatile unsigned g_count;
__device__ volatile unsigned g_sense;

// ---------------------------------------------------------------------------
// Phase A: x_proj GEMM.  C[m][n] = sum_k X[m][k] * Wih[n][k] + bih[n] + bhh[n]
// M = 32768, N = 1024, K = 1024.  Tiles: 128x128, BK=16, 256 thr, 8x8 micro.
// ---------------------------------------------------------------------------
__global__ __launch_bounds__(256) void gemm_xproj_kernel(
    const float* __restrict__ X, const float* __restrict__ W,
    const float* __restrict__ bih, const float* __restrict__ bhh,
    float* __restrict__ C)
{
    __shared__ __align__(16) float As[16][132];   // [k][m], padded stride
    __shared__ __align__(16) float Bs[16][132];   // [k][n]

    const int tid = threadIdx.x;
    const int tm  = tid >> 4;   // 0..15
    const int tn  = tid & 15;   // 0..15
    const int m0  = blockIdx.y * 128;
    const int n0  = blockIdx.x * 128;

    float acc[8][8];
#pragma unroll
    for (int i = 0; i < 8; i++)
#pragma unroll
        for (int j = 0; j < 8; j++) acc[i][j] = 0.0f;

    for (int k0 = 0; k0 < KIN; k0 += 16) {
        float4 av[2], bv[2];
#pragma unroll
        for (int q = 0; q < 2; q++) {
            int idx = tid + q * 256;            // 0..511
            int row = idx >> 2;                 // 0..127
            int k4  = (idx & 3) << 2;           // 0,4,8,12
            av[q] = *(const float4*)(X + (size_t)(m0 + row) * KIN + k0 + k4);
            bv[q] = *(const float4*)(W + (size_t)(n0 + row) * KIN + k0 + k4);
        }
        __syncthreads();
#pragma unroll
        for (int q = 0; q < 2; q++) {
            int idx = tid + q * 256;
            int row = idx >> 2;
            int k4  = (idx & 3) << 2;
            As[k4 + 0][row] = av[q].x; As[k4 + 1][row] = av[q].y;
            As[k4 + 2][row] = av[q].z; As[k4 + 3][row] = av[q].w;
            Bs[k4 + 0][row] = bv[q].x; Bs[k4 + 1][row] = bv[q].y;
            Bs[k4 + 2][row] = bv[q].z; Bs[k4 + 3][row] = bv[q].w;
        }
        __syncthreads();
#pragma unroll
        for (int k = 0; k < 16; k++) {
            float a[8], b[8];
            float4 a0 = *(const float4*)&As[k][tm * 8 + 0];
            float4 a1 = *(const float4*)&As[k][tm * 8 + 4];
            float4 b0 = *(const float4*)&Bs[k][tn * 8 + 0];
            float4 b1 = *(const float4*)&Bs[k][tn * 8 + 4];
            a[0]=a0.x; a[1]=a0.y; a[2]=a0.z; a[3]=a0.w;
            a[4]=a1.x; a[5]=a1.y; a[6]=a1.z; a[7]=a1.w;
            b[0]=b0.x; b[1]=b0.y; b[2]=b0.z; b[3]=b0.w;
            b[4]=b1.x; b[5]=b1.y; b[6]=b1.z; b[7]=b1.w;
#pragma unroll
            for (int i = 0; i < 8; i++)
#pragma unroll
                for (int j = 0; j < 8; j++) acc[i][j] += a[i] * b[j];
        }
    }

    float bias[8];
#pragma unroll
    for (int j = 0; j < 8; j++) {
        int n = n0 + tn * 8 + j;
        bias[j] = bih[n] + bhh[n];
    }
#pragma unroll
    for (int i = 0; i < 8; i++) {
        int m = m0 + tm * 8 + i;
        float4 v0, v1;
        v0.x = acc[i][0] + bias[0]; v0.y = acc[i][1] + bias[1];
        v0.z = acc[i][2] + bias[2]; v0.w = acc[i][3] + bias[3];
        v1.x = acc[i][4] + bias[4]; v1.y = acc[i][5] + bias[5];
        v1.z = acc[i][6] + bias[6]; v1.w = acc[i][7] + bias[7];
        *(float4*)(C + (size_t)m * HN + n0 + tn * 8 + 0) = v0;
        *(float4*)(C + (size_t)m * HN + n0 + tn * 8 + 4) = v1;
    }
}

// ---------------------------------------------------------------------------
// Sense-reversing grid barrier. NBLK blocks must be co-resident.
// State (g_count, g_sense) returns to (0,0) after an EVEN number of barriers.
// ---------------------------------------------------------------------------
__device__ __forceinline__ void gsync(unsigned& sense)
{
    __syncthreads();
    if (threadIdx.x == 0) {
        sense ^= 1u;
        __threadfence();                       // release: prior writes visible
        unsigned old = atomicAdd((unsigned*)&g_count, 1u);
        if (old == NBLK - 1u) {
            g_count = 0;                       // reset BEFORE releasing waiters
            __threadfence();
            g_sense = sense;
        } else {
            while (g_sense != sense) { }
        }
        __threadfence();                       // acquire
    }
    __syncthreads();
}

// ---------------------------------------------------------------------------
// Persistent recurrence kernel. Grid = NBLK blocks x 256 threads.
// Block (ns, ks): N-slice [ns*64, ns*64+64), K-slice [ks*128, ks*128+128).
// W_hh sub-tile staged to SMEM (transposed) ONCE, reused for all 512 steps.
// ---------------------------------------------------------------------------
__global__ __launch_bounds__(256, 1) void rnn_recurrence_kernel(
    const float* __restrict__ Whh, float* __restrict__ out)
{
    __shared__ __align__(16) float Wst[KSL][NS];     // [k][n]  32 KB
    __shared__ __align__(16) float Hst[KSL][BATN];   // [k][b]  32 KB

    const int tid = threadIdx.x;
    const int bid = blockIdx.x;
    const int ks  = bid & 7;            // 0..7
    const int ns  = bid >> 3;           // 0..15
    const int n0  = ns * NS;
    const int k0  = ks * KSL;
    unsigned sense = 0;

    // --- Stage W_hh slice transposed: Wst[k][n] = Whh[n0+n][k0+k] (once) ---
#pragma unroll
    for (int it = 0; it < 8; it++) {
        int idx = it * 256 + tid;       // 0..2047
        int n   = idx & 63;
        int kq  = idx >> 6;             // 0..31 (k-quad)
        float4 v = *(const float4*)(Whh + (size_t)(n0 + n) * KIN + k0 + kq * 4);
        Wst[kq * 4 + 0][n] = v.x; Wst[kq * 4 + 1][n] = v.y;
        Wst[kq * 4 + 2][n] = v.z; Wst[kq * 4 + 3][n] = v.w;
    }

    // --- Step 0: h_0 = tanh(xp_0); disjoint 128-float4 slice per block ---
    if (tid < 128) {
        int fi = bid * 128 + tid;                    // float4 index, 0..16383
        float4 v = ((const float4*)out)[fi];
        v.x = tanhf(v.x); v.y = tanhf(v.y); v.z = tanhf(v.z); v.w = tanhf(v.w);
        ((float4*)out)[fi] = v;
    }
    gsync(sense);                                    // barrier #1

    const int tb  = tid >> 4;           // 0..15 -> bb0 = 4*tb
    const int tn  = tid & 15;           // 0..15 -> nn0 = 4*tn
    const int bb0 = tb * 4;
    const int nn0 = tn * 4;
    float* pb = g_part + (size_t)ks * STEP_ELEMS;

    for (int s = 1; s < SEQN; s++) {
        const float* hprev = out + (size_t)(s - 1) * STEP_ELEMS;
        float*       outs  = out + (size_t)s       * STEP_ELEMS;

        // --- Stage h_{s-1}[b][k0..k0+128) transposed into Hst[k][b] ---
#pragma unroll
        for (int it = 0; it < 8; it++) {
            int idx = it * 256 + tid;   // 0..2047
            int b   = idx & 63;
            int kq  = idx >> 6;         // 0..31
            float4 v = *(const float4*)(hprev + (size_t)b * HN + k0 + kq * 4);
            Hst[kq * 4 + 0][b] = v.x; Hst[kq * 4 + 1][b] = v.y;
            Hst[kq * 4 + 2][b] = v.z; Hst[kq * 4 + 3][b] = v.w;
        }
        __syncthreads();

        // --- Partial GEMM: acc[4][4] over local K range ---
        float acc[4][4];
#pragma unroll
        for (int i = 0; i < 4; i++)
#pragma unroll
            for (int j = 0; j < 4; j++) acc[i][j] = 0.0f;

#pragma unroll 4
        for (int k = 0; k < KSL; k++) {
            float4 a = *(const float4*)&Hst[k][bb0];
            float4 w = *(const float4*)&Wst[k][nn0];
            acc[0][0] += a.x * w.x; acc[0][1] += a.x * w.y;
            acc[0][2] += a.x * w.z; acc[0][3] += a.x * w.w;
            acc[1][0] += a.y * w.x; acc[1][1] += a.y * w.y;
            acc[1][2] += a.y * w.z; acc[1][3] += a.y * w.w;
            acc[2][0] += a.z * w.x; acc[2][1] += a.z * w.y;
            acc[2][2] += a.z * w.z; acc[2][3] += a.z * w.w;
            acc[3][0] += a.w * w.x; acc[3][1] += a.w * w.y;
            acc[3][2] += a.w * w.z; acc[3][3] += a.w * w.w;
        }

        // --- Store partials ---
#pragma unroll
        for (int i = 0; i < 4; i++) {
            float4 v;
            v.x = acc[i][0]; v.y = acc[i][1]; v.z = acc[i][2]; v.w = acc[i][3];
            *(float4*)(pb + (size_t)(bb0 + i) * HN + n0 + nn0) = v;
        }

        gsync(sense);                   // partials visible to all

        // --- Reduce 8 partials + xp, tanh, write h_s (disjoint slices) ---
        if (tid < 128) {
            int fi = bid * 128 + tid;   // float4 index
            float4 v = ((const float4*)outs)[fi];
#pragma unroll
            for (int kp = 0; kp < KSPL; kp++) {
                float4 p = ((const float4*)(g_part + (size_t)kp * STEP_ELEMS))[fi];
                v.x += p.x; v.y += p.y; v.z += p.z; v.w += p.w;
            }
            v.x = tanhf(v.x); v.y = tanhf(v.y);
            v.z = tanhf(v.z); v.w = tanhf(v.w);
            ((float4*)outs)[fi] = v;
        }

        // Skip the final barrier (s==511) to keep the total barrier count
        // EVEN (1022) so g_sense returns to 0 for the next graph replay.
        if (s != SEQN - 1) gsync(sense);
    }
}

// ---------------------------------------------------------------------------
extern "C" void kernel_launch(void* const* d_in, const int* in_sizes, int n_in,
                              void* d_out, int out_size)
{
    const float* X   = (const float*)d_in[0];   // [512, 64, 1024]
    const float* Wih = (const float*)d_in[1];   // [1024, 1024]
    const float* Whh = (const float*)d_in[2];   // [1024, 1024]
    const float* bih = (const float*)d_in[3];   // [1024]
    const float* bhh = (const float*)d_in[4];   // [1024]
    float* out = (float*)d_out;                 // [32768, 1024]

    // Node 1: x_proj for all timesteps, biases fused, written into d_out.
    dim3 gA(HN / 128, (SEQN * BATN) / 128);     // (8, 256)
    gemm_xproj_kernel<<<gA, 256>>>(X, Wih, bih, bhh, out);

    // Node 2: entire recurrence in one persistent kernel.
    rnn_recurrence_kernel<<<NBLK, 256>>>(Whh, out);
}

// round 3
// speedup vs baseline: 1.0570x; 1.0570x over previous
#include <cuda_runtime.h>
#include <math.h>

#define SEQN 512
#define BATN 64
#define KIN  1024
#define HN   1024
#define STEP_ELEMS (BATN * HN)          // 65536 floats per timestep

// Persistent recurrence decomposition: 128 blocks = 8 N-splits x 16 K-splits
#define NBLK 128
#define KSPL 16                         // K splits
#define KSL  64                         // k-range per block
#define NSPL 8                          // N splits
#define NS   128                        // columns per block

// Split-K partial buffer: [KSPL][BATN][HN] = 4 MB
__device__ float g_part[KSPL * BATN * HN];

// Flag-based grid barrier state (zero-initialized; returns to zero per call)
__device__ volatile unsigned g_flags[NBLK * 32];   // 128B stride per block
__device__ volatile unsigned g_sense;

// ---------------------------------------------------------------------------
// Phase A: x_proj GEMM.  C[m][n] = sum_k X[m][k] * Wih[n][k] + bih[n] + bhh[n]
// M = 32768, N = 1024, K = 1024. 128x128 tile, BK=16, 256 thr, 8x8 micro.
// Double-buffered smem: one __syncthreads per k-tile, loads overlap FMAs.
// ---------------------------------------------------------------------------
__global__ __launch_bounds__(256) void gemm_xproj_kernel(
    const float* __restrict__ X, const float* __restrict__ W,
    const float* __restrict__ bih, const float* __restrict__ bhh,
    float* __restrict__ C)
{
    __shared__ __align__(16) float As[2][16][132];
    __shared__ __align__(16) float Bs[2][16][132];

    const int tid = threadIdx.x;
    const int tm  = tid >> 4;   // 0..15
    const int tn  = tid & 15;   // 0..15
    const int m0  = blockIdx.y * 128;
    const int n0  = blockIdx.x * 128;

    const int lrow = tid >> 2;            // 0..63 (plus +64 on q=1)
    const int lk4  = (tid & 3) << 2;      // 0,4,8,12

    float acc[8][8];
#pragma unroll
    for (int i = 0; i < 8; i++)
#pragma unroll
        for (int j = 0; j < 8; j++) acc[i][j] = 0.0f;

    // Prologue: load k-tile 0 into smem buffer 0.
    {
        float4 av[2], bv[2];
#pragma unroll
        for (int q = 0; q < 2; q++) {
            int row = lrow + q * 64;
            av[q] = *(const float4*)(X + (size_t)(m0 + row) * KIN + lk4);
            bv[q] = *(const float4*)(W + (size_t)(n0 + row) * KIN + lk4);
        }
#pragma unroll
        for (int q = 0; q < 2; q++) {
            int row = lrow + q * 64;
            As[0][lk4 + 0][row] = av[q].x; As[0][lk4 + 1][row] = av[q].y;
            As[0][lk4 + 2][row] = av[q].z; As[0][lk4 + 3][row] = av[q].w;
            Bs[0][lk4 + 0][row] = bv[q].x; Bs[0][lk4 + 1][row] = bv[q].y;
            Bs[0][lk4 + 2][row] = bv[q].z; Bs[0][lk4 + 3][row] = bv[q].w;
        }
        __syncthreads();
    }

    int cur = 0;
    for (int k0 = 16; k0 < KIN + 16; k0 += 16) {
        const bool has_next = (k0 < KIN);
        float4 av[2], bv[2];
        if (has_next) {
#pragma unroll
            for (int q = 0; q < 2; q++) {
                int row = lrow + q * 64;
                av[q] = *(const float4*)(X + (size_t)(m0 + row) * KIN + k0 + lk4);
                bv[q] = *(const float4*)(W + (size_t)(n0 + row) * KIN + k0 + lk4);
            }
        }
        // Compute on current buffer while loads are in flight.
#pragma unroll
        for (int k = 0; k < 16; k++) {
            float a[8], b[8];
            float4 a0 = *(const float4*)&As[cur][k][tm * 8 + 0];
            float4 a1 = *(const float4*)&As[cur][k][tm * 8 + 4];
            float4 b0 = *(const float4*)&Bs[cur][k][tn * 8 + 0];
            float4 b1 = *(const float4*)&Bs[cur][k][tn * 8 + 4];
            a[0]=a0.x; a[1]=a0.y; a[2]=a0.z; a[3]=a0.w;
            a[4]=a1.x; a[5]=a1.y; a[6]=a1.z; a[7]=a1.w;
            b[0]=b0.x; b[1]=b0.y; b[2]=b0.z; b[3]=b0.w;
            b[4]=b1.x; b[5]=b1.y; b[6]=b1.z; b[7]=b1.w;
#pragma unroll
            for (int i = 0; i < 8; i++)
#pragma unroll
                for (int j = 0; j < 8; j++) acc[i][j] += a[i] * b[j];
        }
        if (has_next) {
            int nxt = cur ^ 1;
#pragma unroll
            for (int q = 0; q < 2; q++) {
                int row = lrow + q * 64;
                As[nxt][lk4 + 0][row] = av[q].x; As[nxt][lk4 + 1][row] = av[q].y;
                As[nxt][lk4 + 2][row] = av[q].z; As[nxt][lk4 + 3][row] = av[q].w;
                Bs[nxt][lk4 + 0][row] = bv[q].x; Bs[nxt][lk4 + 1][row] = bv[q].y;
                Bs[nxt][lk4 + 2][row] = bv[q].z; Bs[nxt][lk4 + 3][row] = bv[q].w;
            }
            __syncthreads();
            cur = nxt;
        }
    }

    float bias[8];
#pragma unroll
    for (int j = 0; j < 8; j++) {
        int n = n0 + tn * 8 + j;
        bias[j] = bih[n] + bhh[n];
    }
#pragma unroll
    for (int i = 0; i < 8; i++) {
        int m = m0 + tm * 8 + i;
        float4 v0, v1;
        v0.x = acc[i][0] + bias[0]; v0.y = acc[i][1] + bias[1];
        v0.z = acc[i][2] + bias[2]; v0.w = acc[i][3] + bias[3];
        v1.x = acc[i][4] + bias[4]; v1.y = acc[i][5] + bias[5];
        v1.z = acc[i][6] + bias[6]; v1.w = acc[i][7] + bias[7];
        *(float4*)(C + (size_t)m * HN + n0 + tn * 8 + 0) = v0;
        *(float4*)(C + (size_t)m * HN + n0 + tn * 8 + 4) = v1;
    }
}

// ---------------------------------------------------------------------------
// Flag-based sense-reversing grid barrier. No contended atomics:
// each block stores its sense to a distinct 128B-strided flag; block 0's
// first 128 threads poll one flag each, then broadcast via g_sense.
// State returns to all-zero after an EVEN number of barriers.
// ---------------------------------------------------------------------------
__device__ __forceinline__ void gsync(unsigned& sense)
{
    const unsigned ns = sense ^ 1u;
    __syncthreads();
    if (blockIdx.x == 0) {
        if (threadIdx.x == 0) {
            __threadfence();                   // release
            g_flags[0] = ns;
        }
        if (threadIdx.x < NBLK) {
            while (g_flags[threadIdx.x * 32] != ns) { }
        }
        __syncthreads();
        if (threadIdx.x == 0) {
            __threadfence();                   // acquire (all flags seen)
            g_sense = ns;
        }
        __syncthreads();
    } else {
        if (threadIdx.x == 0) {
            __threadfence();                   // release
            g_flags[blockIdx.x * 32] = ns;
            while (g_sense != ns) { }
            __threadfence();                   // acquire
        }
        __syncthreads();
    }
    sense = ns;
}

// ---------------------------------------------------------------------------
// Persistent recurrence kernel. Grid = 128 blocks x 256 threads.
// Block (ns, ks): N-slice [ns*128, +128), K-slice [ks*64, +64).
// W_hh sub-tile (64k x 128n = 32 KB) staged transposed ONCE, reused 511x.
// Micro-tile 8 batches x 4 cols -> FMA-bound inner loop (LDS 25% under FMA).
// ---------------------------------------------------------------------------
__global__ __launch_bounds__(256, 1) void rnn_recurrence_kernel(
    const float* __restrict__ Whh, float* __restrict__ out)
{
    __shared__ __align__(16) float Wst[KSL][NS];     // [k][n]  32 KB
    __shared__ __align__(16) float Hst[KSL][BATN];   // [k][b]  16 KB

    const int tid = threadIdx.x;
    const int bid = blockIdx.x;
    const int ks  = bid & 15;           // 0..15
    const int ns  = bid >> 4;           // 0..7
    const int n0  = ns * NS;
    const int k0  = ks * KSL;
    unsigned sense = 0;

    // --- Stage W_hh slice transposed: Wst[k][n] = Whh[n0+n][k0+k] (once) ---
#pragma unroll
    for (int it = 0; it < 8; it++) {
        int idx = it * 256 + tid;       // 0..2047
        int n   = idx & 127;
        int kq  = idx >> 7;             // 0..15 (k-quad)
        float4 v = *(const float4*)(Whh + (size_t)(n0 + n) * KIN + k0 + kq * 4);
        Wst[kq * 4 + 0][n] = v.x; Wst[kq * 4 + 1][n] = v.y;
        Wst[kq * 4 + 2][n] = v.z; Wst[kq * 4 + 3][n] = v.w;
    }

    // --- Step 0: h_0 = tanh(xp_0); disjoint 128-float4 slice per block ---
    if (tid < 128) {
        int fi = bid * 128 + tid;                    // float4 index, 0..16383
        float4 v = ((const float4*)out)[fi];
        v.x = tanhf(v.x); v.y = tanhf(v.y); v.z = tanhf(v.z); v.w = tanhf(v.w);
        ((float4*)out)[fi] = v;
    }
    gsync(sense);                                    // barrier #1

    const int tb  = tid >> 5;           // 0..7  -> bb0 = 8*tb
    const int tn  = tid & 31;           // 0..31 -> nn0 = 4*tn
    const int bb0 = tb * 8;
    const int nn0 = tn * 4;
    float* pb = g_part + (size_t)ks * STEP_ELEMS;

    for (int s = 1; s < SEQN; s++) {
        const float* hprev = out + (size_t)(s - 1) * STEP_ELEMS;
        float*       outs  = out + (size_t)s       * STEP_ELEMS;

        // --- Stage h_{s-1}[b][k0..k0+64) transposed into Hst[k][b] ---
#pragma unroll
        for (int it = 0; it < 4; it++) {
            int idx = it * 256 + tid;   // 0..1023
            int b   = idx & 63;
            int kq  = idx >> 6;         // 0..15
            float4 v = *(const float4*)(hprev + (size_t)b * HN + k0 + kq * 4);
            Hst[kq * 4 + 0][b] = v.x; Hst[kq * 4 + 1][b] = v.y;
            Hst[kq * 4 + 2][b] = v.z; Hst[kq * 4 + 3][b] = v.w;
        }
        __syncthreads();

        // --- Partial GEMM: 8x4 micro-tile over local 64-k range ---
        float acc[8][4];
#pragma unroll
        for (int i = 0; i < 8; i++)
#pragma unroll
            for (int j = 0; j < 4; j++) acc[i][j] = 0.0f;

#pragma unroll 8
        for (int k = 0; k < KSL; k++) {
            float4 a0 = *(const float4*)&Hst[k][bb0 + 0];
            float4 a1 = *(const float4*)&Hst[k][bb0 + 4];
            float4 w  = *(const float4*)&Wst[k][nn0];
            acc[0][0] += a0.x * w.x; acc[0][1] += a0.x * w.y;
            acc[0][2] += a0.x * w.z; acc[0][3] += a0.x * w.w;
            acc[1][0] += a0.y * w.x; acc[1][1] += a0.y * w.y;
            acc[1][2] += a0.y * w.z; acc[1][3] += a0.y * w.w;
            acc[2][0] += a0.z * w.x; acc[2][1] += a0.z * w.y;
            acc[2][2] += a0.z * w.z; acc[2][3] += a0.z * w.w;
            acc[3][0] += a0.w * w.x; acc[3][1] += a0.w * w.y;
            acc[3][2] += a0.w * w.z; acc[3][3] += a0.w * w.w;
            acc[4][0] += a1.x * w.x; acc[4][1] += a1.x * w.y;
            acc[4][2] += a1.x * w.z; acc[4][3] += a1.x * w.w;
            acc[5][0] += a1.y * w.x; acc[5][1] += a1.y * w.y;
            acc[5][2] += a1.y * w.z; acc[5][3] += a1.y * w.w;
            acc[6][0] += a1.z * w.x; acc[6][1] += a1.z * w.y;
            acc[6][2] += a1.z * w.z; acc[6][3] += a1.z * w.w;
            acc[7][0] += a1.w * w.x; acc[7][1] += a1.w * w.y;
            acc[7][2] += a1.w * w.z; acc[7][3] += a1.w * w.w;
        }

        // --- Store partials (coalesced 512B per warp-row) ---
#pragma unroll
        for (int i = 0; i < 8; i++) {
            float4 v;
            v.x = acc[i][0]; v.y = acc[i][1]; v.z = acc[i][2]; v.w = acc[i][3];
            *(float4*)(pb + (size_t)(bb0 + i) * HN + n0 + nn0) = v;
        }

        gsync(sense);                   // partials visible to all

        // --- Reduce 16 partials + xp, tanh, write h_s (disjoint slices) ---
        if (tid < 128) {
            int fi = bid * 128 + tid;   // float4 index
            float4 v = ((const float4*)outs)[fi];
#pragma unroll
            for (int kp = 0; kp < KSPL; kp++) {
                float4 p = ((const float4*)(g_part + (size_t)kp * STEP_ELEMS))[fi];
                v.x += p.x; v.y += p.y; v.z += p.z; v.w += p.w;
            }
            v.x = tanhf(v.x); v.y = tanhf(v.y);
            v.z = tanhf(v.z); v.w = tanhf(v.w);
            ((float4*)outs)[fi] = v;
        }

        // Skip the final barrier (s==511): keeps total barrier count EVEN
        // (1022) so g_sense/g_flags return to 0 for the next graph replay.
        if (s != SEQN - 1) gsync(sense);
        else __syncthreads();
    }
}

// ---------------------------------------------------------------------------
extern "C" void kernel_launch(void* const* d_in, const int* in_sizes, int n_in,
                              void* d_out, int out_size)
{
    const float* X   = (const float*)d_in[0];   // [512, 64, 1024]
    const float* Wih = (const float*)d_in[1];   // [1024, 1024]
    const float* Whh = (const float*)d_in[2];   // [1024, 1024]
    const float* bih = (const float*)d_in[3];   // [1024]
    const float* bhh = (const float*)d_in[4];   // [1024]
    float* out = (float*)d_out;                 // [32768, 1024]

    // Node 1: x_proj for all timesteps, biases fused, written into d_out.
    dim3 gA(HN / 128, (SEQN * BATN) / 128);     // (8, 256)
    gemm_xproj_kernel<<<gA, 256>>>(X, Wih, bih, bhh, out);

    // Node 2: entire recurrence in one persistent kernel.
    rnn_recurrence_kernel<<<NBLK, 256>>>(Whh, out);
}

// round 6
// speedup vs baseline: 1.1935x; 1.1292x over previous
#include <cuda_runtime.h>
#include <cuda_bf16.h>
#include <math.h>
#include <stdint.h>

#define SEQN 512
#define BATN 64
#define KIN  1024
#define HN   1024
#define STEP_ELEMS (BATN * HN)          // 65536 floats per timestep

// ---------------- static scratch (device globals; no allocs) ----------------
__device__ unsigned short g_xh[SEQN * BATN * KIN];   // bf16 hi of X
__device__ unsigned short g_xl[SEQN * BATN * KIN];   // bf16 lo of X
__device__ unsigned short g_wh[HN * KIN];            // bf16 hi of W_ih
__device__ unsigned short g_wl[HN * KIN];            // bf16 lo of W_ih

// Recurrence split-K partial buffer: [16][BATN][HN] = 4 MB
#define NBLK 128
#define KSPL 16
#define KSL  64
#define NS   128
__device__ float g_part[KSPL * BATN * HN];
__device__ volatile unsigned g_flags[NBLK * 32];
__device__ volatile unsigned g_sense;

// ---------------- warp-MMA helpers (plain sm_103-legal PTX) ----------------
__device__ __forceinline__ uint32_t smem_u32(const void* p) {
    uint32_t a;
    asm("{ .reg .u64 t; cvta.to.shared.u64 t, %1; cvt.u32.u64 %0, t; }"
        : "=r"(a) : "l"(p));
    return a;
}
__device__ __forceinline__ void ldm_x4(uint32_t* r, uint32_t addr) {
    asm volatile("ldmatrix.sync.aligned.m8n8.x4.shared.b16 {%0,%1,%2,%3}, [%4];"
                 : "=r"(r[0]), "=r"(r[1]), "=r"(r[2]), "=r"(r[3]) : "r"(addr));
}
__device__ __forceinline__ void mma_bf16(float* d, const uint32_t* a,
                                         uint32_t b0, uint32_t b1) {
    asm volatile("mma.sync.aligned.m16n8k16.row.col.f32.bf16.bf16.f32 "
                 "{%0,%1,%2,%3}, {%4,%5,%6,%7}, {%8,%9}, {%0,%1,%2,%3};"
                 : "+f"(d[0]), "+f"(d[1]), "+f"(d[2]), "+f"(d[3])
                 : "r"(a[0]), "r"(a[1]), "r"(a[2]), "r"(a[3]), "r"(b0), "r"(b1));
}

// ---------------------------------------------------------------------------
// Split kernels: fp32 -> (bf16 hi, bf16 lo) with lo = bf16(x - float(hi)).
// ---------------------------------------------------------------------------
__device__ __forceinline__ void split4(float4 v, ushort4& h, ushort4& l) {
    __nv_bfloat16 hx = __float2bfloat16(v.x), hy = __float2bfloat16(v.y);
    __nv_bfloat16 hz = __float2bfloat16(v.z), hw = __float2bfloat16(v.w);
    h.x = __bfloat16_as_ushort(hx); h.y = __bfloat16_as_ushort(hy);
    h.z = __bfloat16_as_ushort(hz); h.w = __bfloat16_as_ushort(hw);
    l.x = __bfloat16_as_ushort(__float2bfloat16(v.x - __bfloat162float(hx)));
    l.y = __bfloat16_as_ushort(__float2bfloat16(v.y - __bfloat162float(hy)));
    l.z = __bfloat16_as_ushort(__float2bfloat16(v.z - __bfloat162float(hz)));
    l.w = __bfloat16_as_ushort(__float2bfloat16(v.w - __bfloat162float(hw)));
}
__global__ __launch_bounds__(256) void split_x_kernel(const float* __restrict__ X) {
    size_t i = (size_t)blockIdx.x * 256 + threadIdx.x;
    float4 v = ((const float4*)X)[i];
    ushort4 h, l;
    split4(v, h, l);
    ((ushort4*)g_xh)[i] = h;
    ((ushort4*)g_xl)[i] = l;
}
__global__ __launch_bounds__(256) void split_w_kernel(const float* __restrict__ W) {
    size_t i = (size_t)blockIdx.x * 256 + threadIdx.x;
    float4 v = ((const float4*)W)[i];
    ushort4 h, l;
    split4(v, h, l);
    ((ushort4*)g_wh)[i] = h;
    ((ushort4*)g_wl)[i] = l;
}

// ---------------------------------------------------------------------------
// Phase A via mma.sync bf16x3: C[m][n] = sum_k X[m][k]*W[n][k] + bih[n]+bhh[n]
// Block 128x128, BK=32, 8 warps (4m x 2n), warp tile 32x64.
// smem stride 40 bf16 (80B) -> ldmatrix conflict-free. 3 passes: hh, hl, lh.
// B stored K-major ([n][k]) => NON-trans ldmatrix gives the col-B fragment.
// ---------------------------------------------------------------------------
#define TSTR 40
__global__ __launch_bounds__(256) void gemm_xproj_mma_kernel(
    const float* __restrict__ bih, const float* __restrict__ bhh,
    float* __restrict__ C)
{
    __shared__ __align__(16) unsigned short Ah[128][TSTR];
    __shared__ __align__(16) unsigned short Al[128][TSTR];
    __shared__ __align__(16) unsigned short Bh[128][TSTR];
    __shared__ __align__(16) unsigned short Bl[128][TSTR];
    __shared__ float bs[128];

    const int tid = threadIdx.x;
    const int wid = tid >> 5;
    const int lid = tid & 31;
    const int n0  = blockIdx.x * 128;
    const int m0  = blockIdx.y * 128;
    const int wm  = (wid >> 1) * 32;    // warp m offset within tile (0..96)
    const int wn  = (wid & 1) * 64;     // warp n offset within tile (0,64)

    if (tid < 128) bs[tid] = bih[n0 + tid] + bhh[n0 + tid];

    // Per-thread gmem->smem mapping: 2 uint4 per tile per iter.
    const int lr0 = tid >> 2;             // row 0..63 (+64 for q=1)
    const int lc8 = (tid & 3) * 8;        // bf16 col 0,8,16,24

    // ldmatrix lane addressing: row = (lid&15), k half = (lid>>4)*8
    const int lrow = lid & 15;
    const int lcol = (lid >> 4) * 8;

    float acc[16][4];
#pragma unroll
    for (int t = 0; t < 16; t++)
#pragma unroll
        for (int e = 0; e < 4; e++) acc[t][e] = 0.0f;

    const uint32_t sAh = smem_u32(Ah), sAl = smem_u32(Al);
    const uint32_t sBh = smem_u32(Bh), sBl = smem_u32(Bl);

    for (int kc = 0; kc < KIN / 32; kc++) {
        if (kc) __syncthreads();
        // Load 4 tiles (128 rows x 32 bf16 each).
#pragma unroll
        for (int q = 0; q < 2; q++) {
            int row = lr0 + q * 64;
            size_t gx = (size_t)(m0 + row) * KIN + kc * 32 + lc8;
            size_t gw = (size_t)(n0 + row) * KIN + kc * 32 + lc8;
            *(uint4*)&Ah[row][lc8] = *(const uint4*)(g_xh + gx);
            *(uint4*)&Al[row][lc8] = *(const uint4*)(g_xl + gx);
            *(uint4*)&Bh[row][lc8] = *(const uint4*)(g_wh + gw);
            *(uint4*)&Bl[row][lc8] = *(const uint4*)(g_wl + gw);
        }
        __syncthreads();

#pragma unroll
        for (int ks = 0; ks < 2; ks++) {
            const int kb = ks * 16;
            uint32_t ah[2][4], al[2][4], bh[4][4], bl[4][4];
#pragma unroll
            for (int i = 0; i < 2; i++) {
                uint32_t off = (uint32_t)((wm + 16 * i + lrow) * TSTR + kb + lcol) * 2;
                ldm_x4(ah[i], sAh + off);
                ldm_x4(al[i], sAl + off);
            }
#pragma unroll
            for (int j4 = 0; j4 < 4; j4++) {
                uint32_t off = (uint32_t)((wn + 16 * j4 + lrow) * TSTR + kb + lcol) * 2;
                ldm_x4(bh[j4], sBh + off);   // non-trans: K-major B
                ldm_x4(bl[j4], sBl + off);
            }
#pragma unroll
            for (int i = 0; i < 2; i++)
#pragma unroll
                for (int j = 0; j < 8; j++) {
                    int j4 = j >> 1, sub = j & 1;
                    float* d = acc[i * 8 + j];
                    mma_bf16(d, ah[i], bh[j4][sub], bh[j4][2 + sub]);   // hh
                    mma_bf16(d, ah[i], bl[j4][sub], bl[j4][2 + sub]);   // hl
                    mma_bf16(d, al[i], bh[j4][sub], bh[j4][2 + sub]);   // lh
                }
        }
    }

    // Epilogue: c-frag (i,j): rows m0+wm+16i+(lid>>2)(+8), cols n0+wn+8j+(lid&3)*2
    const int er = lid >> 2;
    const int ec = (lid & 3) * 2;
#pragma unroll
    for (int i = 0; i < 2; i++)
#pragma unroll
        for (int j = 0; j < 8; j++) {
            const float* d = acc[i * 8 + j];
            int cl = wn + 8 * j + ec;           // col within 128-tile
            int row = m0 + wm + 16 * i + er;
            float b0 = bs[cl], b1 = bs[cl + 1];
            float2 v0, v1;
            v0.x = d[0] + b0; v0.y = d[1] + b1;
            v1.x = d[2] + b0; v1.y = d[3] + b1;
            *(float2*)(C + (size_t)row * HN + n0 + cl) = v0;
            *(float2*)(C + (size_t)(row + 8) * HN + n0 + cl) = v1;
        }
}

// ---------------------------------------------------------------------------
// Flag-based sense-reversing grid barrier (unchanged).
// ---------------------------------------------------------------------------
__device__ __forceinline__ void gsync(unsigned& sense)
{
    const unsigned ns = sense ^ 1u;
    __syncthreads();
    if (blockIdx.x == 0) {
        if (threadIdx.x == 0) {
            __threadfence();
            g_flags[0] = ns;
        }
        if (threadIdx.x < NBLK) {
            while (g_flags[threadIdx.x * 32] != ns) { }
        }
        __syncthreads();
        if (threadIdx.x == 0) {
            __threadfence();
            g_sense = ns;
        }
        __syncthreads();
    } else {
        if (threadIdx.x == 0) {
            __threadfence();
            g_flags[blockIdx.x * 32] = ns;
            while (g_sense != ns) { }
            __threadfence();
        }
        __syncthreads();
    }
    sense = ns;
}

// ---------------------------------------------------------------------------
// Persistent recurrence kernel (unchanged from round 3).
// ---------------------------------------------------------------------------
__global__ __launch_bounds__(256, 1) void rnn_recurrence_kernel(
    const float* __restrict__ Whh, float* __restrict__ out)
{
    __shared__ __align__(16) float Wst[KSL][NS];     // [k][n]  32 KB
    __shared__ __align__(16) float Hst[KSL][BATN];   // [k][b]  16 KB

    const int tid = threadIdx.x;
    const int bid = blockIdx.x;
    const int ks  = bid & 15;
    const int ns  = bid >> 4;
    const int n0  = ns * NS;
    const int k0  = ks * KSL;
    unsigned sense = 0;

#pragma unroll
    for (int it = 0; it < 8; it++) {
        int idx = it * 256 + tid;
        int n   = idx & 127;
        int kq  = idx >> 7;
        float4 v = *(const float4*)(Whh + (size_t)(n0 + n) * KIN + k0 + kq * 4);
        Wst[kq * 4 + 0][n] = v.x; Wst[kq * 4 + 1][n] = v.y;
        Wst[kq * 4 + 2][n] = v.z; Wst[kq * 4 + 3][n] = v.w;
    }

    if (tid < 128) {
        int fi = bid * 128 + tid;
        float4 v = ((const float4*)out)[fi];
        v.x = tanhf(v.x); v.y = tanhf(v.y); v.z = tanhf(v.z); v.w = tanhf(v.w);
        ((float4*)out)[fi] = v;
    }
    gsync(sense);

    const int tb  = tid >> 5;
    const int tn  = tid & 31;
    const int bb0 = tb * 8;
    const int nn0 = tn * 4;
    float* pb = g_part + (size_t)ks * STEP_ELEMS;

    for (int s = 1; s < SEQN; s++) {
        const float* hprev = out + (size_t)(s - 1) * STEP_ELEMS;
        float*       outs  = out + (size_t)s       * STEP_ELEMS;

#pragma unroll
        for (int it = 0; it < 4; it++) {
            int idx = it * 256 + tid;
            int b   = idx & 63;
            int kq  = idx >> 6;
            float4 v = *(const float4*)(hprev + (size_t)b * HN + k0 + kq * 4);
            Hst[kq * 4 + 0][b] = v.x; Hst[kq * 4 + 1][b] = v.y;
            Hst[kq * 4 + 2][b] = v.z; Hst[kq * 4 + 3][b] = v.w;
        }
        __syncthreads();

        float acc[8][4];
#pragma unroll
        for (int i = 0; i < 8; i++)
#pragma unroll
            for (int j = 0; j < 4; j++) acc[i][j] = 0.0f;

#pragma unroll 8
        for (int k = 0; k < KSL; k++) {
            float4 a0 = *(const float4*)&Hst[k][bb0 + 0];
            float4 a1 = *(const float4*)&Hst[k][bb0 + 4];
            float4 w  = *(const float4*)&Wst[k][nn0];
            acc[0][0] += a0.x * w.x; acc[0][1] += a0.x * w.y;
            acc[0][2] += a0.x * w.z; acc[0][3] += a0.x * w.w;
            acc[1][0] += a0.y * w.x; acc[1][1] += a0.y * w.y;
            acc[1][2] += a0.y * w.z; acc[1][3] += a0.y * w.w;
            acc[2][0] += a0.z * w.x; acc[2][1] += a0.z * w.y;
            acc[2][2] += a0.z * w.z; acc[2][3] += a0.z * w.w;
            acc[3][0] += a0.w * w.x; acc[3][1] += a0.w * w.y;
            acc[3][2] += a0.w * w.z; acc[3][3] += a0.w * w.w;
            acc[4][0] += a1.x * w.x; acc[4][1] += a1.x * w.y;
            acc[4][2] += a1.x * w.z; acc[4][3] += a1.x * w.w;
            acc[5][0] += a1.y * w.x; acc[5][1] += a1.y * w.y;
            acc[5][2] += a1.y * w.z; acc[5][3] += a1.y * w.w;
            acc[6][0] += a1.z * w.x; acc[6][1] += a1.z * w.y;
            acc[6][2] += a1.z * w.z; acc[6][3] += a1.z * w.w;
            acc[7][0] += a1.w * w.x; acc[7][1] += a1.w * w.y;
            acc[7][2] += a1.w * w.z; acc[7][3] += a1.w * w.w;
        }

#pragma unroll
        for (int i = 0; i < 8; i++) {
            float4 v;
            v.x = acc[i][0]; v.y = acc[i][1]; v.z = acc[i][2]; v.w = acc[i][3];
            *(float4*)(pb + (size_t)(bb0 + i) * HN + n0 + nn0) = v;
        }

        gsync(sense);

        if (tid < 128) {
            int fi = bid * 128 + tid;
            float4 v = ((const float4*)outs)[fi];
#pragma unroll
            for (int kp = 0; kp < KSPL; kp++) {
                float4 p = ((const float4*)(g_part + (size_t)kp * STEP_ELEMS))[fi];
                v.x += p.x; v.y += p.y; v.z += p.z; v.w += p.w;
            }
            v.x = tanhf(v.x); v.y = tanhf(v.y);
            v.z = tanhf(v.z); v.w = tanhf(v.w);
            ((float4*)outs)[fi] = v;
        }

        if (s != SEQN - 1) gsync(sense);
        else __syncthreads();
    }
}

// ---------------------------------------------------------------------------
extern "C" void kernel_launch(void* const* d_in, const int* in_sizes, int n_in,
                              void* d_out, int out_size)
{
    const float* X   = (const float*)d_in[0];   // [512, 64, 1024]
    const float* Wih = (const float*)d_in[1];   // [1024, 1024]
    const float* Whh = (const float*)d_in[2];   // [1024, 1024]
    const float* bih = (const float*)d_in[3];   // [1024]
    const float* bhh = (const float*)d_in[4];   // [1024]
    float* out = (float*)d_out;                 // [32768, 1024]

    // Nodes 1-2: bf16 hi/lo splits of X and W_ih.
    split_x_kernel<<<(SEQN * BATN * KIN / 4) / 256, 256>>>(X);
    split_w_kernel<<<(HN * KIN / 4) / 256, 256>>>(Wih);

    // Node 3: x_proj via mma.sync bf16x3, biases fused, written into d_out.
    dim3 gA(HN / 128, (SEQN * BATN) / 128);     // (8, 256)
    gemm_xproj_mma_kernel<<<gA, 256>>>(bih, bhh, out);

    // Node 4: entire recurrence in one persistent kernel.
    rnn_recurrence_kernel<<<NBLK, 256>>>(Whh, out);
}

// round 7
// speedup vs baseline: 1.4929x; 1.2509x over previous
#include <cuda_runtime.h>
#include <cuda_bf16.h>
#include <math.h>
#include <stdint.h>

#define SEQN 512
#define BATN 64
#define KIN  1024
#define HN   1024
#define STEP_ELEMS (BATN * HN)          // 65536 floats per timestep

// ---------------- static scratch (device globals; no allocs) ----------------
__device__ unsigned short g_xh[SEQN * BATN * KIN];   // bf16 hi of X
__device__ unsigned short g_xl[SEQN * BATN * KIN];   // bf16 lo of X
__device__ unsigned short g_wh[HN * KIN];            // bf16 hi of W_ih
__device__ unsigned short g_wl[HN * KIN];            // bf16 lo of W_ih

// Recurrence: bf16 hi/lo of current h (one timestep, rewritten every step)
__device__ unsigned short g_hh[STEP_ELEMS];
__device__ unsigned short g_hl[STEP_ELEMS];

// Recurrence split-K partial buffer: [8][BATN][HN] = 2 MB
#define NBLK 128
#define R_KSPL 8
#define R_K    128                      // k-range per block
#define R_NS   64                       // n-cols per block
#define RSTR   136                      // padded smem stride (K + 8)
__device__ float g_part[R_KSPL * BATN * HN];
__device__ volatile unsigned g_flags[NBLK * 32];
__device__ volatile unsigned g_sense;

// ---------------- warp-MMA helpers (plain sm_103-legal PTX) ----------------
__device__ __forceinline__ uint32_t smem_u32(const void* p) {
    uint32_t a;
    asm("{ .reg .u64 t; cvta.to.shared.u64 t, %1; cvt.u32.u64 %0, t; }"
        : "=r"(a) : "l"(p));
    return a;
}
__device__ __forceinline__ void ldm_x4(uint32_t* r, uint32_t addr) {
    asm volatile("ldmatrix.sync.aligned.m8n8.x4.shared.b16 {%0,%1,%2,%3}, [%4];"
                 : "=r"(r[0]), "=r"(r[1]), "=r"(r[2]), "=r"(r[3]) : "r"(addr));
}
__device__ __forceinline__ void mma_bf16(float* d, const uint32_t* a,
                                         uint32_t b0, uint32_t b1) {
    asm volatile("mma.sync.aligned.m16n8k16.row.col.f32.bf16.bf16.f32 "
                 "{%0,%1,%2,%3}, {%4,%5,%6,%7}, {%8,%9}, {%0,%1,%2,%3};"
                 : "+f"(d[0]), "+f"(d[1]), "+f"(d[2]), "+f"(d[3])
                 : "r"(a[0]), "r"(a[1]), "r"(a[2]), "r"(a[3]), "r"(b0), "r"(b1));
}

// ---------------------------------------------------------------------------
// fp32 -> (bf16 hi, bf16 lo) split helpers.
// ---------------------------------------------------------------------------
__device__ __forceinline__ void split4(float4 v, ushort4& h, ushort4& l) {
    __nv_bfloat16 hx = __float2bfloat16(v.x), hy = __float2bfloat16(v.y);
    __nv_bfloat16 hz = __float2bfloat16(v.z), hw = __float2bfloat16(v.w);
    h.x = __bfloat16_as_ushort(hx); h.y = __bfloat16_as_ushort(hy);
    h.z = __bfloat16_as_ushort(hz); h.w = __bfloat16_as_ushort(hw);
    l.x = __bfloat16_as_ushort(__float2bfloat16(v.x - __bfloat162float(hx)));
    l.y = __bfloat16_as_ushort(__float2bfloat16(v.y - __bfloat162float(hy)));
    l.z = __bfloat16_as_ushort(__float2bfloat16(v.z - __bfloat162float(hz)));
    l.w = __bfloat16_as_ushort(__float2bfloat16(v.w - __bfloat162float(hw)));
}
__global__ __launch_bounds__(256) void split_x_kernel(const float* __restrict__ X) {
    size_t i = (size_t)blockIdx.x * 256 + threadIdx.x;
    float4 v = ((const float4*)X)[i];
    ushort4 h, l;
    split4(v, h, l);
    ((ushort4*)g_xh)[i] = h;
    ((ushort4*)g_xl)[i] = l;
}
__global__ __launch_bounds__(256) void split_w_kernel(const float* __restrict__ W) {
    size_t i = (size_t)blockIdx.x * 256 + threadIdx.x;
    float4 v = ((const float4*)W)[i];
    ushort4 h, l;
    split4(v, h, l);
    ((ushort4*)g_wh)[i] = h;
    ((ushort4*)g_wl)[i] = l;
}

// ---------------------------------------------------------------------------
// Phase A via mma.sync bf16x3 (unchanged from round 6, PASSING).
// ---------------------------------------------------------------------------
#define TSTR 40
__global__ __launch_bounds__(256) void gemm_xproj_mma_kernel(
    const float* __restrict__ bih, const float* __restrict__ bhh,
    float* __restrict__ C)
{
    __shared__ __align__(16) unsigned short Ah[128][TSTR];
    __shared__ __align__(16) unsigned short Al[128][TSTR];
    __shared__ __align__(16) unsigned short Bh[128][TSTR];
    __shared__ __align__(16) unsigned short Bl[128][TSTR];
    __shared__ float bs[128];

    const int tid = threadIdx.x;
    const int wid = tid >> 5;
    const int lid = tid & 31;
    const int n0  = blockIdx.x * 128;
    const int m0  = blockIdx.y * 128;
    const int wm  = (wid >> 1) * 32;
    const int wn  = (wid & 1) * 64;

    if (tid < 128) bs[tid] = bih[n0 + tid] + bhh[n0 + tid];

    const int lr0 = tid >> 2;
    const int lc8 = (tid & 3) * 8;
    const int lrow = lid & 15;
    const int lcol = (lid >> 4) * 8;

    float acc[16][4];
#pragma unroll
    for (int t = 0; t < 16; t++)
#pragma unroll
        for (int e = 0; e < 4; e++) acc[t][e] = 0.0f;

    const uint32_t sAh = smem_u32(Ah), sAl = smem_u32(Al);
    const uint32_t sBh = smem_u32(Bh), sBl = smem_u32(Bl);

    for (int kc = 0; kc < KIN / 32; kc++) {
        if (kc) __syncthreads();
#pragma unroll
        for (int q = 0; q < 2; q++) {
            int row = lr0 + q * 64;
            size_t gx = (size_t)(m0 + row) * KIN + kc * 32 + lc8;
            size_t gw = (size_t)(n0 + row) * KIN + kc * 32 + lc8;
            *(uint4*)&Ah[row][lc8] = *(const uint4*)(g_xh + gx);
            *(uint4*)&Al[row][lc8] = *(const uint4*)(g_xl + gx);
            *(uint4*)&Bh[row][lc8] = *(const uint4*)(g_wh + gw);
            *(uint4*)&Bl[row][lc8] = *(const uint4*)(g_wl + gw);
        }
        __syncthreads();

#pragma unroll
        for (int ks = 0; ks < 2; ks++) {
            const int kb = ks * 16;
            uint32_t ah[2][4], al[2][4], bh[4][4], bl[4][4];
#pragma unroll
            for (int i = 0; i < 2; i++) {
                uint32_t off = (uint32_t)((wm + 16 * i + lrow) * TSTR + kb + lcol) * 2;
                ldm_x4(ah[i], sAh + off);
                ldm_x4(al[i], sAl + off);
            }
#pragma unroll
            for (int j4 = 0; j4 < 4; j4++) {
                uint32_t off = (uint32_t)((wn + 16 * j4 + lrow) * TSTR + kb + lcol) * 2;
                ldm_x4(bh[j4], sBh + off);
                ldm_x4(bl[j4], sBl + off);
            }
#pragma unroll
            for (int i = 0; i < 2; i++)
#pragma unroll
                for (int j = 0; j < 8; j++) {
                    int j4 = j >> 1, sub = j & 1;
                    float* d = acc[i * 8 + j];
                    mma_bf16(d, ah[i], bh[j4][sub], bh[j4][2 + sub]);
                    mma_bf16(d, ah[i], bl[j4][sub], bl[j4][2 + sub]);
                    mma_bf16(d, al[i], bh[j4][sub], bh[j4][2 + sub]);
                }
        }
    }

    const int er = lid >> 2;
    const int ec = (lid & 3) * 2;
#pragma unroll
    for (int i = 0; i < 2; i++)
#pragma unroll
        for (int j = 0; j < 8; j++) {
            const float* d = acc[i * 8 + j];
            int cl = wn + 8 * j + ec;
            int row = m0 + wm + 16 * i + er;
            float b0 = bs[cl], b1 = bs[cl + 1];
            float2 v0, v1;
            v0.x = d[0] + b0; v0.y = d[1] + b1;
            v1.x = d[2] + b0; v1.y = d[3] + b1;
            *(float2*)(C + (size_t)row * HN + n0 + cl) = v0;
            *(float2*)(C + (size_t)(row + 8) * HN + n0 + cl) = v1;
        }
}

// ---------------------------------------------------------------------------
// Flag-based sense-reversing grid barrier (unchanged).
// ---------------------------------------------------------------------------
__device__ __forceinline__ void gsync(unsigned& sense)
{
    const unsigned ns = sense ^ 1u;
    __syncthreads();
    if (blockIdx.x == 0) {
        if (threadIdx.x == 0) {
            __threadfence();
            g_flags[0] = ns;
        }
        if (threadIdx.x < NBLK) {
            while (g_flags[threadIdx.x * 32] != ns) { }
        }
        __syncthreads();
        if (threadIdx.x == 0) {
            __threadfence();
            g_sense = ns;
        }
        __syncthreads();
    } else {
        if (threadIdx.x == 0) {
            __threadfence();
            g_flags[blockIdx.x * 32] = ns;
            while (g_sense != ns) { }
            __threadfence();
        }
        __syncthreads();
    }
    sense = ns;
}

// ---------------------------------------------------------------------------
// Persistent recurrence kernel, HMMA bf16x3 step GEMM.
// 128 blocks = 16 N-splits x 8 K-splits; per block M=64, N=64, K=128.
// W_hh tile split to bf16 hi/lo in smem ONCE; h exchanged as bf16 hi/lo.
// Dynamic smem: Wh/Wl/Hh/Hl each [64][136] ushort = 68 KB total.
// ---------------------------------------------------------------------------
__global__ __launch_bounds__(256, 1) void rnn_recurrence_mma_kernel(
    const float* __restrict__ Whh, float* __restrict__ out)
{
    extern __shared__ __align__(16) unsigned short sm[];
    unsigned short* Wh = sm;
    unsigned short* Wl = sm + 64 * RSTR;
    unsigned short* Hh = sm + 2 * 64 * RSTR;
    unsigned short* Hl = sm + 3 * 64 * RSTR;

    const int tid = threadIdx.x;
    const int bid = blockIdx.x;
    const int ks  = bid & 7;            // 0..7   K-split
    const int ns  = bid >> 3;           // 0..15  N-split
    const int n0  = ns * R_NS;
    const int k0  = ks * R_K;
    unsigned sense = 0;

    // --- Prologue: split W_hh tile [n0..n0+64) x [k0..k0+128) to bf16 smem ---
#pragma unroll
    for (int it = 0; it < 8; it++) {
        int idx = it * 256 + tid;       // 0..2047 float4s
        int row = idx >> 5;             // 0..63 (n)
        int c4  = (idx & 31) * 4;       // 0..124 (k)
        float4 v = *(const float4*)(Whh + (size_t)(n0 + row) * KIN + k0 + c4);
        ushort4 h, l;
        split4(v, h, l);
        *(ushort4*)&Wh[row * RSTR + c4] = h;
        *(ushort4*)&Wl[row * RSTR + c4] = l;
    }

    // --- Step 0: h_0 = tanh(xp_0), also emit bf16 hi/lo ---
    if (tid < 128) {
        int fi = bid * 128 + tid;       // float4 index over 64x1024
        float4 v = ((const float4*)out)[fi];
        v.x = tanhf(v.x); v.y = tanhf(v.y); v.z = tanhf(v.z); v.w = tanhf(v.w);
        ((float4*)out)[fi] = v;
        ushort4 h, l;
        split4(v, h, l);
        ((ushort4*)g_hh)[fi] = h;
        ((ushort4*)g_hl)[fi] = l;
    }
    gsync(sense);                       // barrier #1

    const int wid  = tid >> 5;
    const int lid  = tid & 31;
    const int wm   = (wid >> 2) * 32;   // warp m offset (0, 32)
    const int wn   = (wid & 3) * 16;    // warp n offset (0,16,32,48)
    const int lrow = lid & 15;
    const int lcol = (lid >> 4) * 8;
    const int er   = lid >> 2;
    const int ec   = (lid & 3) * 2;
    const uint32_t sWh = smem_u32(Wh), sWl = smem_u32(Wl);
    const uint32_t sHh = smem_u32(Hh), sHl = smem_u32(Hl);
    float* pb = g_part + (size_t)ks * STEP_ELEMS;

    for (int s = 1; s < SEQN; s++) {
        float* outs = out + (size_t)s * STEP_ELEMS;

        // --- Stage h_{s-1} bf16 hi/lo slice [64 b][k0..k0+128) ---
#pragma unroll
        for (int it = 0; it < 4; it++) {
            int idx = it * 256 + tid;   // 0..1023 uint4s (8 bf16 each)
            int row = idx >> 4;         // 0..63
            int c8  = (idx & 15) * 8;   // 0..120
            *(uint4*)&Hh[row * RSTR + c8] =
                *(const uint4*)(g_hh + (size_t)row * HN + k0 + c8);
            *(uint4*)&Hl[row * RSTR + c8] =
                *(const uint4*)(g_hl + (size_t)row * HN + k0 + c8);
        }
        __syncthreads();

        // --- HMMA bf16x3: acc[2m][2n8] frags ---
        float acc[4][4];
#pragma unroll
        for (int t = 0; t < 4; t++)
#pragma unroll
            for (int e = 0; e < 4; e++) acc[t][e] = 0.0f;

#pragma unroll
        for (int k16 = 0; k16 < 8; k16++) {
            const int kk = k16 * 16;
            uint32_t ah[2][4], al[2][4], bh[4], bl[4];
#pragma unroll
            for (int i = 0; i < 2; i++) {
                uint32_t off = (uint32_t)((wm + 16 * i + lrow) * RSTR + kk + lcol) * 2;
                ldm_x4(ah[i], sHh + off);
                ldm_x4(al[i], sHl + off);
            }
            {
                uint32_t off = (uint32_t)((wn + lrow) * RSTR + kk + lcol) * 2;
                ldm_x4(bh, sWh + off);
                ldm_x4(bl, sWl + off);
            }
#pragma unroll
            for (int i = 0; i < 2; i++)
#pragma unroll
                for (int j = 0; j < 2; j++) {
                    float* d = acc[i * 2 + j];
                    mma_bf16(d, ah[i], bh[j], bh[2 + j]);   // hh
                    mma_bf16(d, ah[i], bl[j], bl[2 + j]);   // hl
                    mma_bf16(d, al[i], bh[j], bh[2 + j]);   // lh
                }
        }

        // --- Store partials to g_part[ks] ---
#pragma unroll
        for (int i = 0; i < 2; i++)
#pragma unroll
            for (int j = 0; j < 2; j++) {
                const float* d = acc[i * 2 + j];
                int row = wm + 16 * i + er;
                int cn  = n0 + wn + 8 * j + ec;
                float2 v0, v1;
                v0.x = d[0]; v0.y = d[1];
                v1.x = d[2]; v1.y = d[3];
                *(float2*)(pb + (size_t)row * HN + cn) = v0;
                *(float2*)(pb + (size_t)(row + 8) * HN + cn) = v1;
            }

        gsync(sense);                   // partials visible

        // --- Reduce 8 partials + xp, tanh, write h_s fp32 + bf16 hi/lo ---
        if (tid < 128) {
            int fi = bid * 128 + tid;
            float4 v = ((const float4*)outs)[fi];
#pragma unroll
            for (int kp = 0; kp < R_KSPL; kp++) {
                float4 p = ((const float4*)(g_part + (size_t)kp * STEP_ELEMS))[fi];
                v.x += p.x; v.y += p.y; v.z += p.z; v.w += p.w;
            }
            v.x = tanhf(v.x); v.y = tanhf(v.y);
            v.z = tanhf(v.z); v.w = tanhf(v.w);
            ((float4*)outs)[fi] = v;
            ushort4 h, l;
            split4(v, h, l);
            ((ushort4*)g_hh)[fi] = h;
            ((ushort4*)g_hl)[fi] = l;
        }

        // Skip final barrier: total barrier count 1 + 510*2 + 1 = 1022 (even),
        // so g_sense/g_flags return to 0 for the next graph replay.
        if (s != SEQN - 1) gsync(sense);
        else __syncthreads();
    }
}

// ---------------------------------------------------------------------------
extern "C" void kernel_launch(void* const* d_in, const int* in_sizes, int n_in,
                              void* d_out, int out_size)
{
    const float* X   = (const float*)d_in[0];   // [512, 64, 1024]
    const float* Wih = (const float*)d_in[1];   // [1024, 1024]
    const float* Whh = (const float*)d_in[2];   // [1024, 1024]
    const float* bih = (const float*)d_in[3];   // [1024]
    const float* bhh = (const float*)d_in[4];   // [1024]
    float* out = (float*)d_out;                 // [32768, 1024]

    const int rec_smem = 4 * 64 * RSTR * 2;     // 69632 bytes
    cudaFuncSetAttribute(rnn_recurrence_mma_kernel,
                         cudaFuncAttributeMaxDynamicSharedMemorySize, rec_smem);

    // Nodes 1-2: bf16 hi/lo splits of X and W_ih.
    split_x_kernel<<<(SEQN * BATN * KIN / 4) / 256, 256>>>(X);
    split_w_kernel<<<(HN * KIN / 4) / 256, 256>>>(Wih);

    // Node 3: x_proj via mma.sync bf16x3, biases fused, written into d_out.
    dim3 gA(HN / 128, (SEQN * BATN) / 128);     // (8, 256)
    gemm_xproj_mma_kernel<<<gA, 256>>>(bih, bhh, out);

    // Node 4: entire recurrence in one persistent kernel (HMMA step GEMM).
    rnn_recurrence_mma_kernel<<<NBLK, 256, rec_smem>>>(Whh, out);
}